// round 16
// baseline (speedup 1.0000x reference)
#include <cuda_runtime.h>
#include <math.h>

// Problem constants: B=4, C=64, O=64, H=W=128, K=9 taps
__device__ float g_xT [4 * 16384 * 64];   // x transposed to [b][h][w][c]  (16.8 MB)
__device__ float g_off[4 * 16384 * 18];   // offsets [b][h][w][18]         (4.7 MB)
__device__ float g_wT [9 * 64 * 64];      // dc_w rearranged [k][c][o]
__device__ float g_w18[10368];            // off_w rearranged [kk][c4][oc][4]
__device__ float g_y  [4 * 64 * 16384];   // pre-BN conv output, NCHW      (16.8 MB)
__device__ float g_ss [128];              // per-channel scale / shift

__device__ __forceinline__ void fma4(float4& a, float w, const float4 v) {
    a.x = fmaf(w, v.x, a.x);
    a.y = fmaf(w, v.y, a.y);
    a.z = fmaf(w, v.z, a.z);
    a.w = fmaf(w, v.w, a.w);
}

// ---------------------------------------------------------------------------
// K0a: rearrange weights.
// ---------------------------------------------------------------------------
__global__ void k_prep(const float* __restrict__ off_w, const float* __restrict__ dc_w) {
    int idx = blockIdx.x * 256 + threadIdx.x;
    if (idx < 36864) {
        int o = idx & 63, c = (idx >> 6) & 63, k = idx >> 12;
        g_wT[idx] = dc_w[(o * 64 + c) * 9 + k];
    }
    int j = idx - 36864;
    if (j >= 0 && j < 10368) {
        int comp = j & 3;
        int t    = j >> 2;
        int oc   = t % 18;
        int r    = t / 18;
        int c4   = r & 15;
        int kk   = r >> 4;
        g_w18[j] = off_w[(oc * 64 + c4 * 4 + comp) * 9 + kk];
    }
}

// ---------------------------------------------------------------------------
// K0b: transpose x NCHW -> NHWC (g_xT[b][hw][c])
// ---------------------------------------------------------------------------
__global__ void k_transpose(const float* __restrict__ x) {
    __shared__ float tile[32][33];
    int hw0 = blockIdx.x << 5;
    int c0  = blockIdx.y << 5;
    int b   = blockIdx.z;
    int tx  = threadIdx.x, ty = threadIdx.y;
#pragma unroll
    for (int i = 0; i < 4; ++i) {
        int c = c0 + ty + i * 8;
        tile[ty + i * 8][tx] = x[(((size_t)b * 64 + c) << 14) + hw0 + tx];
    }
    __syncthreads();
#pragma unroll
    for (int i = 0; i < 4; ++i) {
        int hw = hw0 + ty + i * 8;
        g_xT[(((size_t)b << 14) + hw) * 64 + c0 + tx] = tile[tx][ty + i * 8];
    }
}

// ---------------------------------------------------------------------------
// K1: offset conv (3x3, C=64 -> 18), zero padding.
// ---------------------------------------------------------------------------
__global__ void __launch_bounds__(256) k_offconv(const float* __restrict__ off_b) {
    __shared__ float4 ws[2592];                 // [kk][c4][oc] as float4 over comp
    int tid = threadIdx.x;
    const float4* wsrc = (const float4*)g_w18;
    for (int i = tid; i < 2592; i += 256) ws[i] = wsrc[i];
    __syncthreads();

    int pidx = (blockIdx.x << 8) + tid;         // 0 .. 65535
    int b = pidx >> 14, hw = pidx & 16383;
    int h = hw >> 7, w = hw & 127;

    float acc[18];
#pragma unroll
    for (int oc = 0; oc < 18; ++oc) acc[oc] = __ldg(off_b + oc);

    const float* xb = g_xT + ((size_t)b << 20);
#pragma unroll
    for (int kk = 0; kk < 9; ++kk) {
        int hy = h + kk / 3 - 1;
        int wx = w + (kk - (kk / 3) * 3) - 1;
        if ((unsigned)hy < 128u && (unsigned)wx < 128u) {
            const float4* src = (const float4*)(xb + (((hy << 7) + wx) << 6));
            const float4* wp  = ws + kk * 288;
#pragma unroll 4
            for (int c4 = 0; c4 < 16; ++c4) {
                float4 xv = src[c4];
                const float4* wq = wp + c4 * 18;
#pragma unroll
                for (int oc = 0; oc < 18; ++oc) {
                    float4 wv = wq[oc];
                    float t0 = fmaf(wv.x, xv.x, acc[oc]);
                    t0 = fmaf(wv.y, xv.y, t0);
                    t0 = fmaf(wv.z, xv.z, t0);
                    acc[oc] = fmaf(wv.w, xv.w, t0);
                }
            }
        }
    }
    float2* outp = (float2*)(g_off + (size_t)pidx * 18);
#pragma unroll
    for (int j2 = 0; j2 < 9; ++j2) outp[j2] = make_float2(acc[2 * j2], acc[2 * j2 + 1]);
}

// ---------------------------------------------------------------------------
// K2: deformable conv, software-pipelined across taps.
// Block = batch b, row h, half-row of 64 pixels; 256 threads.
// Double-buffered sK; one barrier per tap; GEMM weights read directly from
// g_wT (L1-resident, warp-coalesced to 2x16B); gather is streamed (no big
// register arrays), OOB folded into zero weights so loads are unconditional.
// ---------------------------------------------------------------------------
__global__ void __launch_bounds__(256) k_deform(const float* __restrict__ dc_b) {
    __shared__ float offs[1152];        // [p][18]
    __shared__ float sK[2][64][68];     // [buf][c][p] (+pad)

    int tid = threadIdx.x;
    int b  = blockIdx.x >> 8;
    int t  = blockIdx.x & 255;
    int h  = t >> 1;
    int w0 = (t & 1) << 6;
    int pix0 = (b << 14) + (h << 7) + w0;

    {
        const float4* src = (const float4*)(g_off + (size_t)pix0 * 18);
        float4* dst = (float4*)offs;
        for (int i = tid; i < 288; i += 256) dst[i] = src[i];
    }
    const float* xb = g_xT + ((size_t)b << 20);

    int q = tid >> 6, p = tid & 63;     // gather: channels [16q,16q+16), pixel p
    int ty = tid >> 4, tx = tid & 15;   // GEMM: o tile ty*4, p tile tx*4

    // streamed bilinear gather of tap k into sK[buf]
    auto do_gather = [&](int k, int buf) {
        int ky = k / 3;
        int kx = k - ky * 3;
        float dy = offs[p * 18 + 2 * k];
        float dx = offs[p * 18 + 2 * k + 1];
        float py = (float)(h + ky - 1) + dy;
        float px = (float)(w0 + p + kx - 1) + dx;
        float fy = floorf(py), fx = floorf(px);
        int y0 = (int)fy, x0 = (int)fx;
        float ay = py - fy, ax = px - fx;
        float by = 1.0f - ay, bx = 1.0f - ax;
        int y0c = min(max(y0, 0), 127);
        int y1c = min(max(y0 + 1, 0), 127);
        int x0c = min(max(x0, 0), 127);
        int x1c = min(max(x0 + 1, 0), 127);
        bool vy0 = (unsigned)y0 < 128u, vy1 = (unsigned)(y0 + 1) < 128u;
        bool vx0 = (unsigned)x0 < 128u, vx1 = (unsigned)(x0 + 1) < 128u;
        float w00 = (vy0 && vx0) ? by * bx : 0.0f;
        float w01 = (vy0 && vx1) ? by * ax : 0.0f;
        float w10 = (vy1 && vx0) ? ay * bx : 0.0f;
        float w11 = (vy1 && vx1) ? ay * ax : 0.0f;
        const float4* p00 = (const float4*)(xb + (((y0c << 7) + x0c) << 6)) + (q << 2);
        const float4* p01 = (const float4*)(xb + (((y0c << 7) + x1c) << 6)) + (q << 2);
        const float4* p10 = (const float4*)(xb + (((y1c << 7) + x0c) << 6)) + (q << 2);
        const float4* p11 = (const float4*)(xb + (((y1c << 7) + x1c) << 6)) + (q << 2);
        int cb = q << 4;
#pragma unroll
        for (int g = 0; g < 4; ++g) {
            float4 v00 = p00[g], v01 = p01[g], v10 = p10[g], v11 = p11[g];
            float4 r;
            r.x = fmaf(w11, v11.x, fmaf(w10, v10.x, fmaf(w01, v01.x, w00 * v00.x)));
            r.y = fmaf(w11, v11.y, fmaf(w10, v10.y, fmaf(w01, v01.y, w00 * v00.y)));
            r.z = fmaf(w11, v11.z, fmaf(w10, v10.z, fmaf(w01, v01.z, w00 * v00.z)));
            r.w = fmaf(w11, v11.w, fmaf(w10, v10.w, fmaf(w01, v01.w, w00 * v00.w)));
            int c0 = cb + (g << 2);
            sK[buf][c0 + 0][p] = r.x;
            sK[buf][c0 + 1][p] = r.y;
            sK[buf][c0 + 2][p] = r.z;
            sK[buf][c0 + 3][p] = r.w;
        }
    };

    float4 acc0 = make_float4(0.f, 0.f, 0.f, 0.f);
    float4 acc1 = acc0, acc2 = acc0, acc3 = acc0;

    __syncthreads();            // offs visible
    do_gather(0, 0);
    __syncthreads();            // sK[0] ready

#pragma unroll 1
    for (int k = 0; k < 9; ++k) {
        int buf = k & 1;
        // GEMM tap k: weights straight from g_wT via L1 (broadcast-coalesced)
        const float4* wsrc = (const float4*)(g_wT + (k << 12));
#pragma unroll 8
        for (int c = 0; c < 64; ++c) {
            float4 aw = __ldg(wsrc + (c << 4) + ty);
            float4 sv = *(const float4*)&sK[buf][c][tx << 2];
            fma4(acc0, aw.x, sv);
            fma4(acc1, aw.y, sv);
            fma4(acc2, aw.z, sv);
            fma4(acc3, aw.w, sv);
        }
        if (k < 8) do_gather(k + 1, buf ^ 1);
        __syncthreads();
    }

    float4 bias = *(const float4*)(dc_b + (ty << 2));
    acc0.x += bias.x; acc0.y += bias.x; acc0.z += bias.x; acc0.w += bias.x;
    acc1.x += bias.y; acc1.y += bias.y; acc1.z += bias.y; acc1.w += bias.y;
    acc2.x += bias.z; acc2.y += bias.z; acc2.z += bias.z; acc2.w += bias.z;
    acc3.x += bias.w; acc3.y += bias.w; acc3.z += bias.w; acc3.w += bias.w;

    int o0 = ty << 2;
    float* ybase = g_y + (((size_t)((b << 6) + o0)) << 14) + (h << 7) + w0 + (tx << 2);
    *(float4*)(ybase)         = acc0;
    *(float4*)(ybase + 16384) = acc1;
    *(float4*)(ybase + 32768) = acc2;
    *(float4*)(ybase + 49152) = acc3;
}

// ---------------------------------------------------------------------------
// K3: per-channel BN stats over (B,H,W); writes scale/shift.
// ---------------------------------------------------------------------------
__global__ void k_stats(const float* __restrict__ gamma, const float* __restrict__ beta) {
    int o = blockIdx.x, tid = threadIdx.x;
    float s = 0.f, s2 = 0.f;
#pragma unroll
    for (int bb = 0; bb < 4; ++bb) {
        const float4* base = (const float4*)(g_y + (((size_t)((bb << 6) + o)) << 14));
        for (int j = tid; j < 4096; j += 256) {
            float4 v = base[j];
            s += v.x + v.y + v.z + v.w;
            s2 = fmaf(v.x, v.x, s2);
            s2 = fmaf(v.y, v.y, s2);
            s2 = fmaf(v.z, v.z, s2);
            s2 = fmaf(v.w, v.w, s2);
        }
    }
#pragma unroll
    for (int off = 16; off > 0; off >>= 1) {
        s  += __shfl_down_sync(0xffffffffu, s,  off);
        s2 += __shfl_down_sync(0xffffffffu, s2, off);
    }
    __shared__ float rs[8], rs2[8];
    if ((tid & 31) == 0) { rs[tid >> 5] = s; rs2[tid >> 5] = s2; }
    __syncthreads();
    if (tid == 0) {
        float S = 0.f, S2 = 0.f;
#pragma unroll
        for (int i = 0; i < 8; ++i) { S += rs[i]; S2 += rs2[i]; }
        const float inv = 1.0f / 65536.0f;
        float mu   = S * inv;
        float var  = fmaf(S2, inv, -mu * mu);
        float rstd = rsqrtf(var + 1e-5f);
        float sc   = rstd * gamma[o];
        g_ss[o]      = sc;
        g_ss[64 + o] = beta[o] - mu * sc;
    }
}

// ---------------------------------------------------------------------------
// K4: normalize + relu, write final output (NCHW)
// ---------------------------------------------------------------------------
__global__ void k_norm(float* __restrict__ out) {
    int gi = (blockIdx.x << 8) + threadIdx.x;   // float4 index, 1,048,576 total
    int o  = (gi >> 12) & 63;
    float sc = g_ss[o], sh = g_ss[64 + o];
    float4 v = ((const float4*)g_y)[gi];
    float4 r;
    r.x = fmaxf(fmaf(v.x, sc, sh), 0.f);
    r.y = fmaxf(fmaf(v.y, sc, sh), 0.f);
    r.z = fmaxf(fmaf(v.z, sc, sh), 0.f);
    r.w = fmaxf(fmaf(v.w, sc, sh), 0.f);
    ((float4*)out)[gi] = r;
}

// ---------------------------------------------------------------------------
extern "C" void kernel_launch(void* const* d_in, const int* in_sizes, int n_in,
                              void* d_out, int out_size) {
    const float* x     = (const float*)d_in[0];
    const float* off_w = (const float*)d_in[1];
    const float* off_b = (const float*)d_in[2];
    const float* dc_w  = (const float*)d_in[3];
    const float* dc_b  = (const float*)d_in[4];
    const float* gamma = (const float*)d_in[5];
    const float* beta  = (const float*)d_in[6];
    float* out = (float*)d_out;

    k_prep<<<185, 256>>>(off_w, dc_w);

    dim3 tb(32, 8), tg(512, 2, 4);
    k_transpose<<<tg, tb>>>(x);

    k_offconv<<<256, 256>>>(off_b);     // 65536 pixels / 256
    k_deform <<<1024, 256>>>(dc_b);     // 65536 pixels / 64
    k_stats  <<<64, 256>>>(gamma, beta);
    k_norm   <<<4096, 256>>>(out);
}

// round 17
// speedup vs baseline: 1.3105x; 1.3105x over previous
#include <cuda_runtime.h>
#include <math.h>

// Problem constants: B=4, C=64, O=64, H=W=128, K=9 taps
__device__ float  g_xT [4 * 16384 * 64];   // x transposed to [b][h][w][c]  (16.8 MB)
__device__ float  g_off[4 * 16384 * 18];   // offsets [b][h][w][18]         (4.7 MB)
__device__ float2 g_wT2[9 * 64 * 64];      // dc_w rearranged [k][c][o], duplicated {w,w}
__device__ float  g_w18[10368];            // off_w rearranged [kk][c4][oc][4]
__device__ float  g_y  [4 * 64 * 16384];   // pre-BN conv output, NCHW      (16.8 MB)
__device__ float  g_ss [128];              // per-channel scale / shift

__device__ __forceinline__ void fma4(float4& a, float w, const float4 v) {
    a.x = fmaf(w, v.x, a.x);
    a.y = fmaf(w, v.y, a.y);
    a.z = fmaf(w, v.z, a.z);
    a.w = fmaf(w, v.w, a.w);
}

// packed f32x2 FMA: d = a * b + d (per-lane IEEE fp32, sm_103a FFMA2)
__device__ __forceinline__ void ffma2(unsigned long long& d,
                                      unsigned long long a,
                                      unsigned long long b) {
    asm("fma.rn.f32x2 %0, %1, %2, %0;" : "+l"(d) : "l"(a), "l"(b));
}

__device__ __forceinline__ float2 unpack2(unsigned long long v) {
    float lo, hi;
    asm("mov.b64 {%0, %1}, %2;" : "=f"(lo), "=f"(hi) : "l"(v));
    return make_float2(lo, hi);
}

// ---------------------------------------------------------------------------
// K0a: rearrange weights.
//   g_wT2[(k*64+c)*64+o] = {dc_w[(o*64+c)*9+k], same}   (duplicated for f32x2)
//   g_w18[((kk*16+c4)*18+oc)*4+comp] = off_w[(oc*64+c4*4+comp)*9+kk]
// ---------------------------------------------------------------------------
__global__ void k_prep(const float* __restrict__ off_w, const float* __restrict__ dc_w) {
    int idx = blockIdx.x * 256 + threadIdx.x;
    if (idx < 36864) {
        int o = idx & 63, c = (idx >> 6) & 63, k = idx >> 12;
        float w = dc_w[(o * 64 + c) * 9 + k];
        g_wT2[idx] = make_float2(w, w);
    }
    int j = idx - 36864;
    if (j >= 0 && j < 10368) {
        int comp = j & 3;
        int t    = j >> 2;
        int oc   = t % 18;
        int r    = t / 18;
        int c4   = r & 15;
        int kk   = r >> 4;
        g_w18[j] = off_w[(oc * 64 + c4 * 4 + comp) * 9 + kk];
    }
}

// ---------------------------------------------------------------------------
// K0b: transpose x NCHW -> NHWC (g_xT[b][hw][c])
// ---------------------------------------------------------------------------
__global__ void k_transpose(const float* __restrict__ x) {
    __shared__ float tile[32][33];
    int hw0 = blockIdx.x << 5;
    int c0  = blockIdx.y << 5;
    int b   = blockIdx.z;
    int tx  = threadIdx.x, ty = threadIdx.y;
#pragma unroll
    for (int i = 0; i < 4; ++i) {
        int c = c0 + ty + i * 8;
        tile[ty + i * 8][tx] = x[(((size_t)b * 64 + c) << 14) + hw0 + tx];
    }
    __syncthreads();
#pragma unroll
    for (int i = 0; i < 4; ++i) {
        int hw = hw0 + ty + i * 8;
        g_xT[(((size_t)b << 14) + hw) * 64 + c0 + tx] = tile[tx][ty + i * 8];
    }
}

// ---------------------------------------------------------------------------
// K1: offset conv (3x3, C=64 -> 18), zero padding.
// ---------------------------------------------------------------------------
__global__ void __launch_bounds__(256) k_offconv(const float* __restrict__ off_b) {
    __shared__ float4 ws[2592];                 // [kk][c4][oc] as float4 over comp
    int tid = threadIdx.x;
    const float4* wsrc = (const float4*)g_w18;
    for (int i = tid; i < 2592; i += 256) ws[i] = wsrc[i];
    __syncthreads();

    int pidx = (blockIdx.x << 8) + tid;         // 0 .. 65535
    int b = pidx >> 14, hw = pidx & 16383;
    int h = hw >> 7, w = hw & 127;

    float acc[18];
#pragma unroll
    for (int oc = 0; oc < 18; ++oc) acc[oc] = __ldg(off_b + oc);

    const float* xb = g_xT + ((size_t)b << 20);
#pragma unroll
    for (int kk = 0; kk < 9; ++kk) {
        int hy = h + kk / 3 - 1;
        int wx = w + (kk - (kk / 3) * 3) - 1;
        if ((unsigned)hy < 128u && (unsigned)wx < 128u) {
            const float4* src = (const float4*)(xb + (((hy << 7) + wx) << 6));
            const float4* wp  = ws + kk * 288;
#pragma unroll 4
            for (int c4 = 0; c4 < 16; ++c4) {
                float4 xv = src[c4];
                const float4* wq = wp + c4 * 18;
#pragma unroll
                for (int oc = 0; oc < 18; ++oc) {
                    float4 wv = wq[oc];
                    float t0 = fmaf(wv.x, xv.x, acc[oc]);
                    t0 = fmaf(wv.y, xv.y, t0);
                    t0 = fmaf(wv.z, xv.z, t0);
                    acc[oc] = fmaf(wv.w, xv.w, t0);
                }
            }
        }
    }
    float2* outp = (float2*)(g_off + (size_t)pidx * 18);
#pragma unroll
    for (int j2 = 0; j2 < 9; ++j2) outp[j2] = make_float2(acc[2 * j2], acc[2 * j2 + 1]);
}

// ---------------------------------------------------------------------------
// K2: deformable conv. Block = batch b, row h, half-row of 64 pixels; 256 thr.
// Per tap: coalesced bilinear gather (4 threads/pixel -> 64B-contiguous LDGs)
// into registers, sync, STS (sK + duplicated weights), sync, f32x2 GEMM.
// ---------------------------------------------------------------------------
__global__ void __launch_bounds__(256, 3) k_deform(const float* __restrict__ dc_b) {
    extern __shared__ float sm[];
    float*  offs = sm;                      // [p][18]            1152 floats
    float*  sK   = sm + 1152;               // [c][68] (pad)      4352 floats
    float2* WkD  = (float2*)(sm + 5504);    // [c][o] dup pairs   4096 float2

    int tid = threadIdx.x;
    int b  = blockIdx.x >> 8;
    int t  = blockIdx.x & 255;
    int h  = t >> 1;
    int w0 = (t & 1) << 6;
    int pix0 = (b << 14) + (h << 7) + w0;

    {
        const float4* src = (const float4*)(g_off + (size_t)pix0 * 18);
        float4* dst = (float4*)offs;
        for (int i = tid; i < 288; i += 256) dst[i] = src[i];
    }
    const float* xb = g_xT + ((size_t)b << 20);

    int p = tid >> 2, r = tid & 3;          // gather: pixel p, float4-lane r
    int ty = tid >> 4, tx = tid & 15;       // GEMM: o tile ty*4, p tile tx*4

    unsigned long long acc[4][2];
#pragma unroll
    for (int o = 0; o < 4; ++o) { acc[o][0] = 0ull; acc[o][1] = 0ull; }

    __syncthreads();            // offs visible

#pragma unroll 1
    for (int k = 0; k < 9; ++k) {
        // ---- bilinear gather of tap k into registers (coalesced 64B loads)
        int ky = k / 3;
        int kx = k - ky * 3;
        float dy = offs[p * 18 + 2 * k];
        float dx = offs[p * 18 + 2 * k + 1];
        float py = (float)(h + ky - 1) + dy;
        float px = (float)(w0 + p + kx - 1) + dx;
        float fy = floorf(py), fx = floorf(px);
        int y0 = (int)fy, x0 = (int)fx;
        float ay = py - fy, ax = px - fx;
        float by = 1.0f - ay, bx = 1.0f - ax;
        int y0c = min(max(y0, 0), 127);
        int y1c = min(max(y0 + 1, 0), 127);
        int x0c = min(max(x0, 0), 127);
        int x1c = min(max(x0 + 1, 0), 127);
        bool vy0 = (unsigned)y0 < 128u, vy1 = (unsigned)(y0 + 1) < 128u;
        bool vx0 = (unsigned)x0 < 128u, vx1 = (unsigned)(x0 + 1) < 128u;
        float cw[4];
        cw[0] = (vy0 && vx0) ? by * bx : 0.0f;
        cw[1] = (vy0 && vx1) ? by * ax : 0.0f;
        cw[2] = (vy1 && vx0) ? ay * bx : 0.0f;
        cw[3] = (vy1 && vx1) ? ay * ax : 0.0f;
        const float4* cp[4];
        cp[0] = (const float4*)(xb + (((y0c << 7) + x0c) << 6)) + r;
        cp[1] = (const float4*)(xb + (((y0c << 7) + x1c) << 6)) + r;
        cp[2] = (const float4*)(xb + (((y1c << 7) + x0c) << 6)) + r;
        cp[3] = (const float4*)(xb + (((y1c << 7) + x1c) << 6)) + r;

        float4 a0 = make_float4(0.f, 0.f, 0.f, 0.f);
        float4 a1 = a0, a2 = a0, a3 = a0;
#pragma unroll
        for (int cn = 0; cn < 4; ++cn) {
            float wgt = cw[cn];
            const float4* src = cp[cn];
            fma4(a0, wgt, src[0]);
            fma4(a1, wgt, src[4]);
            fma4(a2, wgt, src[8]);
            fma4(a3, wgt, src[12]);
        }

        // ---- prefetch this tap's duplicated weights (32KB) into registers
        const float4* wsrc = (const float4*)(g_wT2 + (k << 12));
        float4 wv0 = wsrc[tid];        float4 wv1 = wsrc[tid + 256];
        float4 wv2 = wsrc[tid + 512];  float4 wv3 = wsrc[tid + 768];
        float4 wv4 = wsrc[tid + 1024]; float4 wv5 = wsrc[tid + 1280];
        float4 wv6 = wsrc[tid + 1536]; float4 wv7 = wsrc[tid + 1792];

        __syncthreads();   // previous GEMM finished reading sK/WkD

        float4* wd = (float4*)WkD;
        wd[tid]        = wv0; wd[tid + 256]  = wv1;
        wd[tid + 512]  = wv2; wd[tid + 768]  = wv3;
        wd[tid + 1024] = wv4; wd[tid + 1280] = wv5;
        wd[tid + 1536] = wv6; wd[tid + 1792] = wv7;

        {
            int cb = r << 2;
            float* d0 = sK + (cb +  0) * 68 + p;
            d0[0] = a0.x; d0[68] = a0.y; d0[136] = a0.z; d0[204] = a0.w;
            float* d1 = sK + (cb + 16) * 68 + p;
            d1[0] = a1.x; d1[68] = a1.y; d1[136] = a1.z; d1[204] = a1.w;
            float* d2 = sK + (cb + 32) * 68 + p;
            d2[0] = a2.x; d2[68] = a2.y; d2[136] = a2.z; d2[204] = a2.w;
            float* d3 = sK + (cb + 48) * 68 + p;
            d3[0] = a3.x; d3[68] = a3.y; d3[136] = a3.z; d3[204] = a3.w;
        }

        __syncthreads();

        // ---- f32x2 GEMM over 64 channels
#pragma unroll 8
        for (int c = 0; c < 64; ++c) {
            const float2* wrow = WkD + (c << 6) + (ty << 2);
            ulonglong2 aw01 = *(const ulonglong2*)(wrow);
            ulonglong2 aw23 = *(const ulonglong2*)(wrow + 2);
            ulonglong2 sv   = *(const ulonglong2*)(sK + c * 68 + (tx << 2));
            ffma2(acc[0][0], aw01.x, sv.x); ffma2(acc[0][1], aw01.x, sv.y);
            ffma2(acc[1][0], aw01.y, sv.x); ffma2(acc[1][1], aw01.y, sv.y);
            ffma2(acc[2][0], aw23.x, sv.x); ffma2(acc[2][1], aw23.x, sv.y);
            ffma2(acc[3][0], aw23.y, sv.x); ffma2(acc[3][1], aw23.y, sv.y);
        }
    }

    float4 bias = *(const float4*)(dc_b + (ty << 2));
    float bv[4] = {bias.x, bias.y, bias.z, bias.w};

    int o0 = ty << 2;
    float* ybase = g_y + (((size_t)((b << 6) + o0)) << 14) + (h << 7) + w0 + (tx << 2);
#pragma unroll
    for (int o = 0; o < 4; ++o) {
        float2 lo = unpack2(acc[o][0]);
        float2 hi = unpack2(acc[o][1]);
        float4 res = make_float4(lo.x + bv[o], lo.y + bv[o], hi.x + bv[o], hi.y + bv[o]);
        *(float4*)(ybase + (size_t)o * 16384) = res;
    }
}

// ---------------------------------------------------------------------------
// K3: per-channel BN stats over (B,H,W); writes scale/shift.
// ---------------------------------------------------------------------------
__global__ void k_stats(const float* __restrict__ gamma, const float* __restrict__ beta) {
    int o = blockIdx.x, tid = threadIdx.x;
    float s = 0.f, s2 = 0.f;
#pragma unroll
    for (int bb = 0; bb < 4; ++bb) {
        const float4* base = (const float4*)(g_y + (((size_t)((bb << 6) + o)) << 14));
        for (int j = tid; j < 4096; j += 256) {
            float4 v = base[j];
            s += v.x + v.y + v.z + v.w;
            s2 = fmaf(v.x, v.x, s2);
            s2 = fmaf(v.y, v.y, s2);
            s2 = fmaf(v.z, v.z, s2);
            s2 = fmaf(v.w, v.w, s2);
        }
    }
#pragma unroll
    for (int off = 16; off > 0; off >>= 1) {
        s  += __shfl_down_sync(0xffffffffu, s,  off);
        s2 += __shfl_down_sync(0xffffffffu, s2, off);
    }
    __shared__ float rs[8], rs2[8];
    if ((tid & 31) == 0) { rs[tid >> 5] = s; rs2[tid >> 5] = s2; }
    __syncthreads();
    if (tid == 0) {
        float S = 0.f, S2 = 0.f;
#pragma unroll
        for (int i = 0; i < 8; ++i) { S += rs[i]; S2 += rs2[i]; }
        const float inv = 1.0f / 65536.0f;
        float mu   = S * inv;
        float var  = fmaf(S2, inv, -mu * mu);
        float rstd = rsqrtf(var + 1e-5f);
        float sc   = rstd * gamma[o];
        g_ss[o]      = sc;
        g_ss[64 + o] = beta[o] - mu * sc;
    }
}

// ---------------------------------------------------------------------------
// K4: normalize + relu, write final output (NCHW)
// ---------------------------------------------------------------------------
__global__ void k_norm(float* __restrict__ out) {
    int gi = (blockIdx.x << 8) + threadIdx.x;   // float4 index, 1,048,576 total
    int o  = (gi >> 12) & 63;
    float sc = g_ss[o], sh = g_ss[64 + o];
    float4 v = ((const float4*)g_y)[gi];
    float4 r;
    r.x = fmaxf(fmaf(v.x, sc, sh), 0.f);
    r.y = fmaxf(fmaf(v.y, sc, sh), 0.f);
    r.z = fmaxf(fmaf(v.z, sc, sh), 0.f);
    r.w = fmaxf(fmaf(v.w, sc, sh), 0.f);
    ((float4*)out)[gi] = r;
}

// ---------------------------------------------------------------------------
extern "C" void kernel_launch(void* const* d_in, const int* in_sizes, int n_in,
                              void* d_out, int out_size) {
    const float* x     = (const float*)d_in[0];
    const float* off_w = (const float*)d_in[1];
    const float* off_b = (const float*)d_in[2];
    const float* dc_w  = (const float*)d_in[3];
    const float* dc_b  = (const float*)d_in[4];
    const float* gamma = (const float*)d_in[5];
    const float* beta  = (const float*)d_in[6];
    float* out = (float*)d_out;

    const int DEFORM_SMEM = (1152 + 4352 + 8192) * 4;   // 54784 bytes
    cudaFuncSetAttribute(k_deform, cudaFuncAttributeMaxDynamicSharedMemorySize,
                         DEFORM_SMEM);

    k_prep<<<185, 256>>>(off_w, dc_w);

    dim3 tb(32, 8), tg(512, 2, 4);
    k_transpose<<<tg, tb>>>(x);

    k_offconv<<<256, 256>>>(off_b);                    // 65536 pixels / 256
    k_deform <<<1024, 256, DEFORM_SMEM>>>(dc_b);       // 65536 pixels / 64
    k_stats  <<<64, 256>>>(gamma, beta);
    k_norm   <<<4096, 256>>>(out);
}